// round 7
// baseline (speedup 1.0000x reference)
#include <cuda_runtime.h>
#include <cstdint>

// ---------------------------------------------------------------------------
// AllPassMORRCirculantConv2d  (B=8, Cin=32, H=W=64, K=3, S=1, P=1, Cout=64)
// out[p*8+k] = sum_q (scale[q]*D) * rcp(K2 - 2AR*cos(phase_{p,q,k}))
// phase_{p,q,k} = sum_j inten[q*8+j] * w[p][q][(k-j)&7]   (circular conv n=8)
//
// R5: pixel-pair f32x2 packing via pre-shifted float2 image (pack MOVs = 0),
//     broadcast-duplicated weights in shared, full q-unroll (immediate
//     addressing), warp-per-p split (8-way) for occupancy.
// ---------------------------------------------------------------------------

#define AA 0.8578
#define RR 0.8985

static constexpr float G2f  = (float)(2.0 * AA * RR);                   // 2AR
static constexpr float K2f  = (float)(1.0 + (AA * RR) * (AA * RR));     // 1+(AR)^2
static constexpr float Df   = (float)((AA * AA + RR * RR) - 1.0
                                      - (AA * RR) * (AA * RR));         // K1-K2
static constexpr float GAINf = 1.6666666666666667f;                     // sqrt(100/36)

#define PH 66
#define PW 66
#define NPAD (8 * 32 * PH * PW)

typedef unsigned long long ull;

// Pre-shifted packed image: g_sq2[i] = { s[i], s[i+1] }, s = padded x^2*gain
__device__ float2 g_sq2[NPAD];

// ---------------- packed f32x2 helpers -------------------------------------
__device__ __forceinline__ ull pack2(float lo, float hi) {
    ull r;
    asm("mov.b64 %0, {%1, %2};" : "=l"(r) : "f"(lo), "f"(hi));
    return r;
}
__device__ __forceinline__ void unpack2(ull v, float& lo, float& hi) {
    asm("mov.b64 {%0, %1}, %2;" : "=f"(lo), "=f"(hi) : "l"(v));
}
__device__ __forceinline__ ull fma2(ull a, ull b, ull c) {
    ull d;
    asm("fma.rn.f32x2 %0, %1, %2, %3;" : "=l"(d) : "l"(a), "l"(b), "l"(c));
    return d;
}

// ---------------- Kernel 1: pad + square + gain + shift-pack ---------------
__device__ __forceinline__ float pad_val(const float* __restrict__ x, int j) {
    int px = j % PW;
    int t  = j / PW;
    int py = t % PH;
    int bc = t / PH;
    if (px >= 1 && px <= 64 && py >= 1 && py <= 64) {
        float u = x[bc * 4096 + (py - 1) * 64 + (px - 1)];
        return u * u * GAINf;
    }
    return 0.0f;
}

__global__ void prep_kernel(const float* __restrict__ x) {
    int i = blockIdx.x * blockDim.x + threadIdx.x;
    if (i >= NPAD) return;
    float v0 = pad_val(x, i);
    float v1 = (i + 1 < NPAD) ? pad_val(x, i + 1) : 0.0f;
    g_sq2[i] = make_float2(v0, v1);
}

// ---------------- Kernel 2: main -------------------------------------------
// block = 256 threads = 32 pixel-pairs x 8 p (warp index = p). grid = 512.
__global__ __launch_bounds__(256, 3)
void morr_main_kernel(const float* __restrict__ weight,   // [8][36][8]
                      const float* __restrict__ mscale,   // [19]
                      float* __restrict__ out)            // [8][64][64][64]
{
    __shared__ ull   sww[8 * 36 * 8];   // {w, w} duplicated pairs
    __shared__ float ss2[36];           // scale[q] * D

    const int tid = threadIdx.x;
    for (int i = tid; i < 2304; i += 256) {
        float wv = weight[i];
        sww[i] = pack2(wv, wv);
    }
    for (int i = tid; i < 36; i += 256) {
        float s = (i < 18) ? mscale[i] : -mscale[i - 18];
        ss2[i] = s * Df;
    }
    __syncthreads();

    const int lane   = tid & 31;
    const int p      = tid >> 5;                 // warp index = output block p
    const int pairid = blockIdx.x * 32 + lane;   // 0..16383
    const int pix0   = pairid * 2;               // even pixel of the pair
    const int b      = pix0 >> 12;
    const int y      = (pix0 >> 6) & 63;
    const int x      = pix0 & 63;                // even

    const float2* base  = g_sq2 + b * (32 * PH * PW) + y * PW + x;
    const ull*    wbase = sww + p * 288;

    // acc[k]   : pixel x   , channel p*8+k
    // acc[8+k] : pixel x+1 , channel p*8+k
    float acc[16];
#pragma unroll
    for (int i = 0; i < 16; i++) acc[i] = 0.0f;

#pragma unroll
    for (int q = 0; q < 36; q++) {
        ull inten2[8];
#pragma unroll
        for (int t = 0; t < 8; t++) {
            const int w = q * 8 + t;
            const int c = w / 9;
            const int r = w % 9;
            inten2[t] = *reinterpret_cast<const ull*>(
                base + c * (PH * PW) + (r / 3) * PW + (r % 3));
        }
        ull w2[8];
#pragma unroll
        for (int m = 0; m < 8; m++) w2[m] = wbase[q * 8 + m];

        ull ph2[8] = {0ull, 0ull, 0ull, 0ull, 0ull, 0ull, 0ull, 0ull};
#pragma unroll
        for (int j = 0; j < 8; j++) {
#pragma unroll
            for (int k = 0; k < 8; k++)
                ph2[k] = fma2(inten2[j], w2[(k - j) & 7], ph2[k]);
        }

        const float s2 = ss2[q];
#pragma unroll
        for (int k = 0; k < 8; k++) {
            float p0, p1;
            unpack2(ph2[k], p0, p1);
            float c0 = __cosf(p0);
            float c1 = __cosf(p1);
            float d0 = fmaf(-G2f, c0, K2f);
            float d1 = fmaf(-G2f, c1, K2f);
            float r0, r1;
            asm("rcp.approx.f32 %0, %1;" : "=f"(r0) : "f"(d0));
            asm("rcp.approx.f32 %0, %1;" : "=f"(r1) : "f"(d1));
            acc[k]     = fmaf(s2, r0, acc[k]);
            acc[8 + k] = fmaf(s2, r1, acc[8 + k]);
        }
    }

    float* op = out + (b * 64 + p * 8) * 4096 + y * 64 + x;
#pragma unroll
    for (int k = 0; k < 8; k++)
        *reinterpret_cast<float2*>(op + k * 4096) = make_float2(acc[k], acc[8 + k]);
}

// ---------------- launch ----------------------------------------------------
extern "C" void kernel_launch(void* const* d_in, const int* in_sizes, int n_in,
                              void* d_out, int out_size)
{
    const float* x   = (const float*)d_in[0];   // (8,32,64,64)
    const float* wgt = (const float*)d_in[1];   // (8,36,8)
    const float* ms  = (const float*)d_in[2];   // (19,)
    float* out = (float*)d_out;                 // (8,64,64,64)

    prep_kernel<<<(NPAD + 255) / 256, 256>>>(x);
    morr_main_kernel<<<512, 256>>>(wgt, ms, out);
}

// round 8
// speedup vs baseline: 2.4036x; 2.4036x over previous
#include <cuda_runtime.h>
#include <cstdint>

// ---------------------------------------------------------------------------
// AllPassMORRCirculantConv2d  (B=8, Cin=32, H=W=64, K=3, S=1, P=1, Cout=64)
// out[p*8+k] = sum_q (scale[q]*D) * rcp(K2 - 2AR*cos(phase_{p,q,k}))
// phase_{p,q,k} = sum_j inten[q*8+j] * w[p][q][(k-j)&7]   (circular conv n=8)
//
// R7: pixel-pair f32x2 math (R5) + SHARED-staged input tile (fixes R5's 8x
//     duplicated global traffic). Block = one image row: 32 pairs x 8 p-warps.
// ---------------------------------------------------------------------------

#define AA 0.8578
#define RR 0.8985

static constexpr float G2f  = (float)(2.0 * AA * RR);                   // 2AR
static constexpr float K2f  = (float)(1.0 + (AA * RR) * (AA * RR));     // 1+(AR)^2
static constexpr float Df   = (float)((AA * AA + RR * RR) - 1.0
                                      - (AA * RR) * (AA * RR));         // K1-K2
static constexpr float GAINf = 1.6666666666666667f;                     // sqrt(100/36)

#define PH 66
#define PW 66
#define NPAD (8 * 32 * PH * PW)

typedef unsigned long long ull;

// Pre-shifted packed image: g_sq2[i] = { s[i], s[i+1] }, s = padded x^2*gain
__device__ float2 g_sq2[NPAD];

// ---------------- packed f32x2 helpers -------------------------------------
__device__ __forceinline__ ull pack2(float lo, float hi) {
    ull r;
    asm("mov.b64 %0, {%1, %2};" : "=l"(r) : "f"(lo), "f"(hi));
    return r;
}
__device__ __forceinline__ void unpack2(ull v, float& lo, float& hi) {
    asm("mov.b64 {%0, %1}, %2;" : "=f"(lo), "=f"(hi) : "l"(v));
}
__device__ __forceinline__ ull fma2(ull a, ull b, ull c) {
    ull d;
    asm("fma.rn.f32x2 %0, %1, %2, %3;" : "=l"(d) : "l"(a), "l"(b), "l"(c));
    return d;
}

// ---------------- Kernel 1: pad + square + gain + shift-pack ---------------
__device__ __forceinline__ float pad_val(const float* __restrict__ x, int j) {
    int px = j % PW;
    int t  = j / PW;
    int py = t % PH;
    int bc = t / PH;
    if (px >= 1 && px <= 64 && py >= 1 && py <= 64) {
        float u = x[bc * 4096 + (py - 1) * 64 + (px - 1)];
        return u * u * GAINf;
    }
    return 0.0f;
}

__global__ void prep_kernel(const float* __restrict__ x) {
    int i = blockIdx.x * blockDim.x + threadIdx.x;
    if (i >= NPAD) return;
    float v0 = pad_val(x, i);
    float v1 = (i + 1 < NPAD) ? pad_val(x, i + 1) : 0.0f;
    g_sq2[i] = make_float2(v0, v1);
}

// ---------------- Kernel 2: main -------------------------------------------
// block = 256 threads = 8 p-warps x 32 pixel-pairs (one row). grid = 512.
__global__ __launch_bounds__(256, 3)
void morr_main_kernel(const float* __restrict__ weight,   // [8][36][8]
                      const float* __restrict__ mscale,   // [19]
                      float* __restrict__ out)            // [8][64][64][64]
{
    __shared__ float2   sp[32 * 3 * 66];   // staged window pairs: 50688 B
    __shared__ ull      sww[8 * 36 * 8];   // {w,w} duplicated:    18432 B
    __shared__ float    ss2[36];           // scale[q] * D
    __shared__ unsigned stab[288];         // element offsets into sp

    const int tid = threadIdx.x;
    const int b   = blockIdx.x >> 6;       // image
    const int y   = blockIdx.x & 63;       // row

    for (int i = tid; i < 2304; i += 256) {
        float wv = weight[i];
        sww[i] = pack2(wv, wv);
    }
    if (tid < 36) {
        float s = (tid < 18) ? mscale[tid] : -mscale[tid - 18];
        ss2[tid] = s * Df;
    }
    for (int i = tid; i < 288; i += 256) {
        int c = i / 9, r = i % 9;
        stab[i] = (unsigned)((c * 3 + r / 3) * 66 + (r % 3));
    }
    // Stage input: channels 0..31, padded rows y..y+2, pair-cols 0..65
    {
        const float2* gsrc = g_sq2 + (b * 32) * (PH * PW);
        for (int i = tid; i < 32 * 3 * 66; i += 256) {
            int c   = i / 198;
            int rem = i - c * 198;
            int rr  = rem / 66;
            int pc  = rem - rr * 66;
            sp[i] = gsrc[(c * PH + y + rr) * PW + pc];
        }
    }
    __syncthreads();

    const int lane = tid & 31;
    const int p    = tid >> 5;                       // warp index = output block
    const int x    = lane * 2;                       // even pixel of the pair

    const float2* spx   = sp + x;                    // +stab[] = window pair
    const ull*    wbase = sww + p * 288;

    // acc[k] : pixel x ; acc[8+k] : pixel x+1   (channel p*8+k)
    float acc[16];
#pragma unroll
    for (int i = 0; i < 16; i++) acc[i] = 0.0f;

#pragma unroll 1
    for (int q = 0; q < 36; q++) {
        ull inten2[8];
#pragma unroll
        for (int t = 0; t < 8; t++)
            inten2[t] = *reinterpret_cast<const ull*>(spx + stab[q * 8 + t]);

        ull w2[8];
#pragma unroll
        for (int m = 0; m < 8; m++) w2[m] = wbase[q * 8 + m];

        ull ph2[8] = {0ull, 0ull, 0ull, 0ull, 0ull, 0ull, 0ull, 0ull};
#pragma unroll
        for (int j = 0; j < 8; j++) {
#pragma unroll
            for (int k = 0; k < 8; k++)
                ph2[k] = fma2(inten2[j], w2[(k - j) & 7], ph2[k]);
        }

        const float s2 = ss2[q];
#pragma unroll
        for (int k = 0; k < 8; k++) {
            float p0, p1;
            unpack2(ph2[k], p0, p1);
            float c0 = __cosf(p0);
            float c1 = __cosf(p1);
            float d0 = fmaf(-G2f, c0, K2f);
            float d1 = fmaf(-G2f, c1, K2f);
            float r0, r1;
            asm("rcp.approx.f32 %0, %1;" : "=f"(r0) : "f"(d0));
            asm("rcp.approx.f32 %0, %1;" : "=f"(r1) : "f"(d1));
            acc[k]     = fmaf(s2, r0, acc[k]);
            acc[8 + k] = fmaf(s2, r1, acc[8 + k]);
        }
    }

    float* op = out + (b * 64 + p * 8) * 4096 + y * 64 + x;
#pragma unroll
    for (int k = 0; k < 8; k++)
        *reinterpret_cast<float2*>(op + k * 4096) = make_float2(acc[k], acc[8 + k]);
}

// ---------------- launch ----------------------------------------------------
extern "C" void kernel_launch(void* const* d_in, const int* in_sizes, int n_in,
                              void* d_out, int out_size)
{
    const float* x   = (const float*)d_in[0];   // (8,32,64,64)
    const float* wgt = (const float*)d_in[1];   // (8,36,8)
    const float* ms  = (const float*)d_in[2];   // (19,)
    float* out = (float*)d_out;                 // (8,64,64,64)

    prep_kernel<<<(NPAD + 255) / 256, 256>>>(x);
    morr_main_kernel<<<512, 256>>>(wgt, ms, out);
}